// round 12
// baseline (speedup 1.0000x reference)
#include <cuda_runtime.h>

#define Tv 512
#define ROWW 60                 // 56 data + 4 pad floats per seq row (240B)
#define STAGEF (32 * ROWW)
#define WBYTES (3 * STAGEF * 4)             // per-warp staging bytes
#define SMEM_BYTES (4 * WBYTES + 256)       // 4 warps + STRs

__device__ float gA[8192 * 8];
__device__ float gU[8192 * 8];
__device__ int   gXF[8192], gXB[8192];
__device__ float gNF[8192], gNB[8192];
__device__ int   gCF[8192], gCB[8192];

static __device__ __forceinline__ void cpa16(void* dst, const void* src) {
    unsigned d = (unsigned)__cvta_generic_to_shared(dst);
    asm volatile("cp.async.cg.shared.global [%0], [%1], 16;" :: "r"(d), "l"(src));
}
#define CP_COMMIT() asm volatile("cp.async.commit_group;")
#define CP_WAIT2()  asm volatile("cp.async.wait_group 2;")

__global__ void __launch_bounds__(128, 1)
crf_half_kernel(const float* __restrict__ em,
                const int* __restrict__ labels,
                const int* __restrict__ mask,
                const float* __restrict__ startT,
                const float* __restrict__ endT,
                const float* __restrict__ trans)
{
    extern __shared__ char dsm[];
    const int tid  = threadIdx.x;
    const int wid  = tid >> 5;
    const int lane = tid & 31;

    float* ES   = (float*)(dsm + wid * WBYTES);        // this warp's 3-stage ring
    float* STRs = (float*)(dsm + 4 * WBYTES);

    for (int i = tid; i < 49; i += 128) STRs[i] = trans[i];
    __syncthreads();

    const int group = blockIdx.x * 2 + (wid >> 1);     // 0..255
    const int half  = wid & 1;                          // 0 = forward, 1 = backward
    const int seq   = group * 32 + lane;

    const float* emb = em + (size_t)(group * 32) * (Tv * 7);
    const int4* lb4 = (const int4*)(labels + (size_t)seq * Tv);
    const int4* mb4 = (const int4*)(mask   + (size_t)seq * Tv);

    float E[7][7];
#pragma unroll
    for (int i = 0; i < 7; i++)
#pragma unroll
        for (int j = 0; j < 7; j++)
            E[i][j] = __expf(__ldg(&trans[i * 7 + j]));

#define STAGE(SLOT, MM) do { \
    float* _d = ES + (SLOT) * STAGEF; \
    _Pragma("unroll") \
    for (int i = 0; i < 14; i++) { \
        int idx = i * 32 + lane; int r = (idx * 4682) >> 16; int c = idx - r * 14; \
        cpa16(_d + r * ROWW + c * 4, emb + (size_t)r * (Tv * 7) + (MM) * 56 + c * 4); \
    } \
    CP_COMMIT(); } while (0)

    float st[7];
    float num = 0.f;
    int cnt = 0, xs = 0;

#define RENORM() do { \
    float mx = st[0]; \
    _Pragma("unroll") for (int j = 1; j < 7; j++) mx = fmaxf(mx, st[j]); \
    int ex = (__float_as_int(mx) >> 23) & 0xFF; \
    float inv = __int_as_float((254 - ex) << 23); \
    xs += ex - 127; \
    _Pragma("unroll") for (int j = 0; j < 7; j++) st[j] *= inv; } while (0)

    if (half == 0) {
        // ======================= FORWARD: t in [0,256) =======================
        auto FST = [&](const float* e) {
            float q[7];
#pragma unroll
            for (int j = 0; j < 7; j++) q[j] = st[0] * E[0][j];
#pragma unroll
            for (int i = 1; i < 7; i++)
#pragma unroll
                for (int j = 0; j < 7; j++) q[j] = fmaf(st[i], E[i][j], q[j]);
#pragma unroll
            for (int j = 0; j < 7; j++) st[j] = q[j] * __expf(e[j]);
        };
        auto SST = [&](const float* e, int M) {
            float q[7];
#pragma unroll
            for (int j = 0; j < 7; j++) q[j] = st[0] * E[0][j];
#pragma unroll
            for (int i = 1; i < 7; i++)
#pragma unroll
                for (int j = 0; j < 7; j++) q[j] = fmaf(st[i], E[i][j], q[j]);
#pragma unroll
            for (int j = 0; j < 7; j++) {
                float v = q[j] * __expf(e[j]);
                st[j] = M ? v : st[j];
            }
        };

        STAGE(0, 0); STAGE(1, 1); STAGE(2, 2);
        int4 lc0 = __ldg(lb4 + 0), lc1 = __ldg(lb4 + 1);
        int4 mc0 = __ldg(mb4 + 0), mc1 = __ldg(mb4 + 1);
        CP_WAIT2(); __syncwarp();

        int carry;
        // ---- macro 0 (peeled): init t=0, steps 1..7 ----
        {
            const float* r = ES + lane * ROWW;
            int la[8] = {lc0.x, lc0.y, lc0.z, lc0.w, lc1.x, lc1.y, lc1.z, lc1.w};
            int ma[8] = {mc0.x, mc0.y, mc0.z, mc0.w, mc1.x, mc1.y, mc1.z, mc1.w};
            lc0 = __ldg(lb4 + 2); lc1 = __ldg(lb4 + 3);
            mc0 = __ldg(mb4 + 2); mc1 = __ldg(mb4 + 3);

            int prevL = 0;
#pragma unroll
            for (int s = 0; s < 8; s++) {
                int L = la[s] < 0 ? 0 : la[s];
                if (s == 0) {
                    num = __ldg(startT + L) + r[L];
                } else {
                    float v = STRs[prevL * 7 + L] + r[s * 7 + L];
                    num += ma[s] ? v : 0.f;
                }
                cnt += ma[s] ? 1 : 0;
                prevL = L;
            }
            carry = prevL;

#pragma unroll
            for (int j = 0; j < 7; j++) st[j] = __expf(__ldg(startT + j) + r[j]);
            RENORM();
#pragma unroll
            for (int s = 1; s < 8; s++) SST(r + s * 7, ma[s]);
            RENORM();
            __syncwarp();
            STAGE(0, 3);
        }

#pragma unroll 1
        for (int m = 1; m < 32; m++) {
            CP_WAIT2(); __syncwarp();
            const float* r = ES + (m % 3) * STAGEF + lane * ROWW;
            int la[8] = {lc0.x, lc0.y, lc0.z, lc0.w, lc1.x, lc1.y, lc1.z, lc1.w};
            int ma[8] = {mc0.x, mc0.y, mc0.z, mc0.w, mc1.x, mc1.y, mc1.z, mc1.w};
            if (m < 31) {
                lc0 = __ldg(lb4 + 2 * m + 2); lc1 = __ldg(lb4 + 2 * m + 3);
                mc0 = __ldg(mb4 + 2 * m + 2); mc1 = __ldg(mb4 + 2 * m + 3);
            }

            int prevL = carry;
#pragma unroll
            for (int s = 0; s < 8; s++) {
                int L = la[s] < 0 ? 0 : la[s];
                float v = STRs[prevL * 7 + L] + r[s * 7 + L];
                num += ma[s] ? v : 0.f;
                cnt += ma[s] ? 1 : 0;
                prevL = L;
            }
            carry = prevL;

            int am = ma[0] & ma[1] & ma[2] & ma[3] & ma[4] & ma[5] & ma[6] & ma[7];
            if (__all_sync(0xFFFFFFFFu, am)) {
#pragma unroll
                for (int s = 0; s < 8; s++) FST(r + s * 7);
            } else {
#pragma unroll
                for (int s = 0; s < 8; s++) SST(r + s * 7, ma[s]);
            }
            RENORM();
            __syncwarp();
            if (m + 3 < 32) STAGE((m + 3) % 3, m + 3); else CP_COMMIT();
        }

#pragma unroll
        for (int j = 0; j < 7; j++) gA[seq * 8 + j] = st[j];
        gXF[seq] = xs; gNF[seq] = num; gCF[seq] = cnt;

    } else {
        // ======================= BACKWARD: t in [256,512) =======================
        auto BFST = [&](const float* e) {
            float w[7];
#pragma unroll
            for (int j = 0; j < 7; j++) w[j] = st[j] * __expf(e[j]);
            float q[7];
#pragma unroll
            for (int i = 0; i < 7; i++) q[i] = w[0] * E[i][0];
#pragma unroll
            for (int j = 1; j < 7; j++)
#pragma unroll
                for (int i = 0; i < 7; i++) q[i] = fmaf(w[j], E[i][j], q[i]);
#pragma unroll
            for (int i = 0; i < 7; i++) st[i] = q[i];
        };
        auto BSST = [&](const float* e, int M) {
            float w[7];
#pragma unroll
            for (int j = 0; j < 7; j++) w[j] = st[j] * __expf(e[j]);
            float q[7];
#pragma unroll
            for (int i = 0; i < 7; i++) q[i] = w[0] * E[i][0];
#pragma unroll
            for (int j = 1; j < 7; j++)
#pragma unroll
                for (int i = 0; i < 7; i++) q[i] = fmaf(w[j], E[i][j], q[i]);
#pragma unroll
            for (int i = 0; i < 7; i++) st[i] = M ? q[i] : st[i];
        };

        STAGE(0, 63); STAGE(1, 62); STAGE(2, 61);
        int4 lc0 = __ldg(lb4 + 126), lc1 = __ldg(lb4 + 127);
        int4 mc0 = __ldg(mb4 + 126), mc1 = __ldg(mb4 + 127);

#pragma unroll
        for (int j = 0; j < 7; j++) st[j] = __expf(__ldg(endT + j));

        CP_WAIT2(); __syncwarp();

        int pendL = 0, pendM = 0;
#pragma unroll 1
        for (int k = 0; k < 32; k++) {
            if (k > 0) { CP_WAIT2(); __syncwarp(); }
            const float* r = ES + (k % 3) * STAGEF + lane * ROWW;
            int la[8] = {lc0.x, lc0.y, lc0.z, lc0.w, lc1.x, lc1.y, lc1.z, lc1.w};
            int ma[8] = {mc0.x, mc0.y, mc0.z, mc0.w, mc1.x, mc1.y, mc1.z, mc1.w};
            if (k < 31) {
                int nm = 63 - k - 1;
                lc0 = __ldg(lb4 + 2 * nm);     lc1 = __ldg(lb4 + 2 * nm + 1);
                mc0 = __ldg(mb4 + 2 * nm);     mc1 = __ldg(mb4 + 2 * nm + 1);
            }

            // ---- numerator for this macro's times (chain-free) ----
            int L0 = la[0] < 0 ? 0 : la[0];
            int P = L0;
#pragma unroll
            for (int s = 1; s < 8; s++) {
                int L = la[s] < 0 ? 0 : la[s];
                float v = STRs[P * 7 + L] + r[s * 7 + L];
                num += ma[s] ? v : 0.f;
                cnt += ma[s] ? 1 : 0;
                P = L;
            }
            // close pending cross-macro trans term with this macro's last label (P)
            num += pendM ? STRs[P * 7 + pendL] : 0.f;
            // s=0: emission now; its trans term pends on the next (earlier) macro
            num += ma[0] ? r[L0] : 0.f;
            cnt += ma[0] ? 1 : 0;
            pendL = L0; pendM = ma[0];

            // ---- recursion, descending time ----
            int am = ma[0] & ma[1] & ma[2] & ma[3] & ma[4] & ma[5] & ma[6] & ma[7];
            if (__all_sync(0xFFFFFFFFu, am)) {
#pragma unroll
                for (int s = 7; s >= 0; s--) BFST(r + s * 7);
            } else {
#pragma unroll
                for (int s = 7; s >= 0; s--) BSST(r + s * 7, ma[s]);
            }
            RENORM();
            __syncwarp();
            if (k + 3 < 32) STAGE((k + 3) % 3, 63 - (k + 3)); else CP_COMMIT();
        }

        // close final pending term against label t=255
        int L255 = __ldg(labels + (size_t)seq * Tv + 255);
        L255 = L255 < 0 ? 0 : L255;
        num += pendM ? STRs[L255 * 7 + pendL] : 0.f;

#pragma unroll
        for (int j = 0; j < 7; j++) gU[seq * 8 + j] = st[j];
        gXB[seq] = xs; gNB[seq] = num; gCB[seq] = cnt;
    }

#undef STAGE
#undef RENORM
}

__global__ void __launch_bounds__(256)
combine_kernel(const int* __restrict__ labels,
               const float* __restrict__ endT,
               float* __restrict__ out)
{
    const int seq = blockIdx.x * 256 + threadIdx.x;
    float acc = 0.f;
#pragma unroll
    for (int j = 0; j < 7; j++) acc = fmaf(gA[seq * 8 + j], gU[seq * 8 + j], acc);
    float den = __logf(acc) + (float)(gXF[seq] + gXB[seq]) * 0.69314718055994531f;

    int c = gCF[seq] + gCB[seq];
    int li = c > 0 ? c - 1 : 0;
    int lt = __ldg(labels + (size_t)seq * Tv + li);
    lt = lt < 0 ? 0 : lt;
    float num = gNF[seq] + gNB[seq] + __ldg(endT + lt);

    float v = den - num;
#pragma unroll
    for (int off = 16; off > 0; off >>= 1)
        v += __shfl_xor_sync(0xFFFFFFFFu, v, off);
    if ((threadIdx.x & 31) == 0) atomicAdd(out, v);
}

extern "C" void kernel_launch(void* const* d_in, const int* in_sizes, int n_in,
                              void* d_out, int out_size)
{
    const float* em     = (const float*)d_in[0];
    const int*   labels = (const int*)  d_in[1];
    const int*   mask   = (const int*)  d_in[2];
    const float* startT = (const float*)d_in[3];
    const float* endT   = (const float*)d_in[4];
    const float* trans  = (const float*)d_in[5];

    cudaFuncSetAttribute(crf_half_kernel, cudaFuncAttributeMaxDynamicSharedMemorySize, SMEM_BYTES);
    cudaMemsetAsync(d_out, 0, sizeof(float));
    crf_half_kernel<<<128, 128, SMEM_BYTES>>>(em, labels, mask, startT, endT, trans);
    combine_kernel<<<32, 256>>>(labels, endT, (float*)d_out);
}

// round 13
// speedup vs baseline: 1.0604x; 1.0604x over previous
#include <cuda_runtime.h>

#define Tv 512
#define ROWW 60                 // 56 data + 4 pad floats per seq row (240B)
#define STAGEF (32 * ROWW)

__device__ float gA[8192 * 8];
__device__ float gU[8192 * 8];
__device__ int   gXF[8192], gXB[8192];
__device__ float gNF[8192], gNB[8192];
__device__ int   gCF[8192], gCB[8192];

static __device__ __forceinline__ void cpa16(void* dst, const void* src) {
    unsigned d = (unsigned)__cvta_generic_to_shared(dst);
    asm volatile("cp.async.cg.shared.global [%0], [%1], 16;" :: "r"(d), "l"(src));
}
#define CP_COMMIT() asm volatile("cp.async.commit_group;")
#define CP_WAIT2()  asm volatile("cp.async.wait_group 2;")

__global__ void __launch_bounds__(32, 1)
crf_half_kernel(const float* __restrict__ em,
                const int* __restrict__ labels,
                const int* __restrict__ mask,
                const float* __restrict__ startT,
                const float* __restrict__ endT,
                const float* __restrict__ trans)
{
    __shared__ float ES[3 * STAGEF];
    __shared__ float STRs[49];

    const int lane  = threadIdx.x;
    const int half  = blockIdx.x >> 8;       // 0 = forward, 1 = backward
    const int group = blockIdx.x & 255;
    const int seq   = group * 32 + lane;

    const float* emb = em + (size_t)(group * 32) * (Tv * 7);
    const int4* lb4 = (const int4*)(labels + (size_t)seq * Tv);
    const int4* mb4 = (const int4*)(mask   + (size_t)seq * Tv);

    for (int i = lane; i < 49; i += 32) STRs[i] = trans[i];
    __syncwarp();

    float E[7][7];
#pragma unroll
    for (int i = 0; i < 7; i++)
#pragma unroll
        for (int j = 0; j < 7; j++)
            E[i][j] = __expf(__ldg(&trans[i * 7 + j]));

#define STAGE(SLOT, MM) do { \
    float* _d = ES + (SLOT) * STAGEF; \
    _Pragma("unroll") \
    for (int i = 0; i < 14; i++) { \
        int idx = i * 32 + lane; int r = (idx * 4682) >> 16; int c = idx - r * 14; \
        cpa16(_d + r * ROWW + c * 4, emb + (size_t)r * (Tv * 7) + (MM) * 56 + c * 4); \
    } \
    CP_COMMIT(); } while (0)

    // batch-load 28 floats (4 steps) via 7x LDS.128 and exp them all up front
#define LOADG(ROWP, G, XE) do { \
    const float4* _q4 = (const float4*)((ROWP) + (G) * 28); \
    _Pragma("unroll") \
    for (int c = 0; c < 7; c++) { \
        float4 _v = _q4[c]; \
        XE[4*c+0] = _v.x; XE[4*c+1] = _v.y; XE[4*c+2] = _v.z; XE[4*c+3] = _v.w; \
    } \
    _Pragma("unroll") \
    for (int k = 0; k < 28; k++) XE[k] = __expf(XE[k]); } while (0)

    float st[7];
    float num = 0.f;
    int cnt = 0, xs = 0;

#define RENORM() do { \
    float mx = st[0]; \
    _Pragma("unroll") for (int j = 1; j < 7; j++) mx = fmaxf(mx, st[j]); \
    int ex = (__float_as_int(mx) >> 23) & 0xFF; \
    float inv = __int_as_float((254 - ex) << 23); \
    xs += ex - 127; \
    _Pragma("unroll") for (int j = 0; j < 7; j++) st[j] *= inv; } while (0)

    if (half == 0) {
        // ======================= FORWARD: t in [0,256) =======================
        auto FSTX = [&](const float* x) {        // x = pre-exp'd emissions
            float q[7];
#pragma unroll
            for (int j = 0; j < 7; j++) q[j] = st[0] * E[0][j];
#pragma unroll
            for (int i = 1; i < 7; i++)
#pragma unroll
                for (int j = 0; j < 7; j++) q[j] = fmaf(st[i], E[i][j], q[j]);
#pragma unroll
            for (int j = 0; j < 7; j++) st[j] = q[j] * x[j];
        };
        auto SSTX = [&](const float* x, int M) {
            float q[7];
#pragma unroll
            for (int j = 0; j < 7; j++) q[j] = st[0] * E[0][j];
#pragma unroll
            for (int i = 1; i < 7; i++)
#pragma unroll
                for (int j = 0; j < 7; j++) q[j] = fmaf(st[i], E[i][j], q[j]);
#pragma unroll
            for (int j = 0; j < 7; j++) {
                float v = q[j] * x[j];
                st[j] = M ? v : st[j];
            }
        };

        STAGE(0, 0); STAGE(1, 1); STAGE(2, 2);
        int4 lc0 = __ldg(lb4 + 0), lc1 = __ldg(lb4 + 1);
        int4 mc0 = __ldg(mb4 + 0), mc1 = __ldg(mb4 + 1);
        CP_WAIT2(); __syncwarp();

        int carry;
        // ---- macro 0 (peeled): init t=0, steps 1..7 ----
        {
            const float* r = ES + lane * ROWW;
            int la[8] = {lc0.x, lc0.y, lc0.z, lc0.w, lc1.x, lc1.y, lc1.z, lc1.w};
            int ma[8] = {mc0.x, mc0.y, mc0.z, mc0.w, mc1.x, mc1.y, mc1.z, mc1.w};
            lc0 = __ldg(lb4 + 2); lc1 = __ldg(lb4 + 3);
            mc0 = __ldg(mb4 + 2); mc1 = __ldg(mb4 + 3);

            int prevL = 0;
#pragma unroll
            for (int s = 0; s < 8; s++) {
                int L = la[s] < 0 ? 0 : la[s];
                if (s == 0) {
                    num = __ldg(startT + L) + r[L];
                } else {
                    float v = STRs[prevL * 7 + L] + r[s * 7 + L];
                    num += ma[s] ? v : 0.f;
                }
                cnt += ma[s] ? 1 : 0;
                prevL = L;
            }
            carry = prevL;

#pragma unroll
            for (int j = 0; j < 7; j++) st[j] = __expf(__ldg(startT + j) + r[j]);
            RENORM();
            {
                float xe[28]; LOADG(r, 0, xe);
                SSTX(xe + 7,  ma[1]); SSTX(xe + 14, ma[2]); SSTX(xe + 21, ma[3]);
            }
            {
                float xe[28]; LOADG(r, 1, xe);
                SSTX(xe + 0,  ma[4]); SSTX(xe + 7,  ma[5]);
                SSTX(xe + 14, ma[6]); SSTX(xe + 21, ma[7]);
            }
            RENORM();
            __syncwarp();
            STAGE(0, 3);
        }

#pragma unroll 1
        for (int m = 1; m < 32; m++) {
            CP_WAIT2(); __syncwarp();
            const float* r = ES + (m % 3) * STAGEF + lane * ROWW;
            int la[8] = {lc0.x, lc0.y, lc0.z, lc0.w, lc1.x, lc1.y, lc1.z, lc1.w};
            int ma[8] = {mc0.x, mc0.y, mc0.z, mc0.w, mc1.x, mc1.y, mc1.z, mc1.w};
            if (m < 31) {
                lc0 = __ldg(lb4 + 2 * m + 2); lc1 = __ldg(lb4 + 2 * m + 3);
                mc0 = __ldg(mb4 + 2 * m + 2); mc1 = __ldg(mb4 + 2 * m + 3);
            }

            int prevL = carry;
#pragma unroll
            for (int s = 0; s < 8; s++) {
                int L = la[s] < 0 ? 0 : la[s];
                float v = STRs[prevL * 7 + L] + r[s * 7 + L];
                num += ma[s] ? v : 0.f;
                cnt += ma[s] ? 1 : 0;
                prevL = L;
            }
            carry = prevL;

            int am = ma[0] & ma[1] & ma[2] & ma[3] & ma[4] & ma[5] & ma[6] & ma[7];
            if (__all_sync(0xFFFFFFFFu, am)) {
                { float xe[28]; LOADG(r, 0, xe);
                  FSTX(xe + 0); FSTX(xe + 7); FSTX(xe + 14); FSTX(xe + 21); }
                { float xe[28]; LOADG(r, 1, xe);
                  FSTX(xe + 0); FSTX(xe + 7); FSTX(xe + 14); FSTX(xe + 21); }
            } else {
                { float xe[28]; LOADG(r, 0, xe);
                  SSTX(xe + 0,  ma[0]); SSTX(xe + 7,  ma[1]);
                  SSTX(xe + 14, ma[2]); SSTX(xe + 21, ma[3]); }
                { float xe[28]; LOADG(r, 1, xe);
                  SSTX(xe + 0,  ma[4]); SSTX(xe + 7,  ma[5]);
                  SSTX(xe + 14, ma[6]); SSTX(xe + 21, ma[7]); }
            }
            RENORM();
            __syncwarp();
            if (m + 3 < 32) STAGE((m + 3) % 3, m + 3); else CP_COMMIT();
        }

#pragma unroll
        for (int j = 0; j < 7; j++) gA[seq * 8 + j] = st[j];
        gXF[seq] = xs; gNF[seq] = num; gCF[seq] = cnt;

    } else {
        // ======================= BACKWARD: t in [256,512) =======================
        auto BFSTX = [&](const float* x) {
            float w[7];
#pragma unroll
            for (int j = 0; j < 7; j++) w[j] = st[j] * x[j];
            float q[7];
#pragma unroll
            for (int i = 0; i < 7; i++) q[i] = w[0] * E[i][0];
#pragma unroll
            for (int j = 1; j < 7; j++)
#pragma unroll
                for (int i = 0; i < 7; i++) q[i] = fmaf(w[j], E[i][j], q[i]);
#pragma unroll
            for (int i = 0; i < 7; i++) st[i] = q[i];
        };
        auto BSSTX = [&](const float* x, int M) {
            float w[7];
#pragma unroll
            for (int j = 0; j < 7; j++) w[j] = st[j] * x[j];
            float q[7];
#pragma unroll
            for (int i = 0; i < 7; i++) q[i] = w[0] * E[i][0];
#pragma unroll
            for (int j = 1; j < 7; j++)
#pragma unroll
                for (int i = 0; i < 7; i++) q[i] = fmaf(w[j], E[i][j], q[i]);
#pragma unroll
            for (int i = 0; i < 7; i++) st[i] = M ? q[i] : st[i];
        };

        STAGE(0, 63); STAGE(1, 62); STAGE(2, 61);
        int4 lc0 = __ldg(lb4 + 126), lc1 = __ldg(lb4 + 127);
        int4 mc0 = __ldg(mb4 + 126), mc1 = __ldg(mb4 + 127);

#pragma unroll
        for (int j = 0; j < 7; j++) st[j] = __expf(__ldg(endT + j));

        CP_WAIT2(); __syncwarp();

        int pendL = 0, pendM = 0;
#pragma unroll 1
        for (int k = 0; k < 32; k++) {
            if (k > 0) { CP_WAIT2(); __syncwarp(); }
            const float* r = ES + (k % 3) * STAGEF + lane * ROWW;
            int la[8] = {lc0.x, lc0.y, lc0.z, lc0.w, lc1.x, lc1.y, lc1.z, lc1.w};
            int ma[8] = {mc0.x, mc0.y, mc0.z, mc0.w, mc1.x, mc1.y, mc1.z, mc1.w};
            if (k < 31) {
                int nm = 63 - k - 1;
                lc0 = __ldg(lb4 + 2 * nm);     lc1 = __ldg(lb4 + 2 * nm + 1);
                mc0 = __ldg(mb4 + 2 * nm);     mc1 = __ldg(mb4 + 2 * nm + 1);
            }

            // ---- numerator for this macro's times (chain-free) ----
            int L0 = la[0] < 0 ? 0 : la[0];
            int P = L0;
#pragma unroll
            for (int s = 1; s < 8; s++) {
                int L = la[s] < 0 ? 0 : la[s];
                float v = STRs[P * 7 + L] + r[s * 7 + L];
                num += ma[s] ? v : 0.f;
                cnt += ma[s] ? 1 : 0;
                P = L;
            }
            // close pending cross-macro trans term with this macro's last label (P)
            num += pendM ? STRs[P * 7 + pendL] : 0.f;
            // s=0: emission now; its trans term pends on the next (earlier) macro
            num += ma[0] ? r[L0] : 0.f;
            cnt += ma[0] ? 1 : 0;
            pendL = L0; pendM = ma[0];

            // ---- recursion, descending time ----
            int am = ma[0] & ma[1] & ma[2] & ma[3] & ma[4] & ma[5] & ma[6] & ma[7];
            if (__all_sync(0xFFFFFFFFu, am)) {
                { float xe[28]; LOADG(r, 1, xe);
                  BFSTX(xe + 21); BFSTX(xe + 14); BFSTX(xe + 7); BFSTX(xe + 0); }
                { float xe[28]; LOADG(r, 0, xe);
                  BFSTX(xe + 21); BFSTX(xe + 14); BFSTX(xe + 7); BFSTX(xe + 0); }
            } else {
                { float xe[28]; LOADG(r, 1, xe);
                  BSSTX(xe + 21, ma[7]); BSSTX(xe + 14, ma[6]);
                  BSSTX(xe + 7,  ma[5]); BSSTX(xe + 0,  ma[4]); }
                { float xe[28]; LOADG(r, 0, xe);
                  BSSTX(xe + 21, ma[3]); BSSTX(xe + 14, ma[2]);
                  BSSTX(xe + 7,  ma[1]); BSSTX(xe + 0,  ma[0]); }
            }
            RENORM();
            __syncwarp();
            if (k + 3 < 32) STAGE((k + 3) % 3, 63 - (k + 3)); else CP_COMMIT();
        }

        // close final pending term against label t=255
        int L255 = __ldg(labels + (size_t)seq * Tv + 255);
        L255 = L255 < 0 ? 0 : L255;
        num += pendM ? STRs[L255 * 7 + pendL] : 0.f;

#pragma unroll
        for (int j = 0; j < 7; j++) gU[seq * 8 + j] = st[j];
        gXB[seq] = xs; gNB[seq] = num; gCB[seq] = cnt;
    }

#undef STAGE
#undef LOADG
#undef RENORM
}

__global__ void __launch_bounds__(256)
combine_kernel(const int* __restrict__ labels,
               const float* __restrict__ endT,
               float* __restrict__ out)
{
    const int seq = blockIdx.x * 256 + threadIdx.x;
    float acc = 0.f;
#pragma unroll
    for (int j = 0; j < 7; j++) acc = fmaf(gA[seq * 8 + j], gU[seq * 8 + j], acc);
    float den = __logf(acc) + (float)(gXF[seq] + gXB[seq]) * 0.69314718055994531f;

    int c = gCF[seq] + gCB[seq];
    int li = c > 0 ? c - 1 : 0;
    int lt = __ldg(labels + (size_t)seq * Tv + li);
    lt = lt < 0 ? 0 : lt;
    float num = gNF[seq] + gNB[seq] + __ldg(endT + lt);

    float v = den - num;
#pragma unroll
    for (int off = 16; off > 0; off >>= 1)
        v += __shfl_xor_sync(0xFFFFFFFFu, v, off);
    if ((threadIdx.x & 31) == 0) atomicAdd(out, v);
}

extern "C" void kernel_launch(void* const* d_in, const int* in_sizes, int n_in,
                              void* d_out, int out_size)
{
    const float* em     = (const float*)d_in[0];
    const int*   labels = (const int*)  d_in[1];
    const int*   mask   = (const int*)  d_in[2];
    const float* startT = (const float*)d_in[3];
    const float* endT   = (const float*)d_in[4];
    const float* trans  = (const float*)d_in[5];

    cudaMemsetAsync(d_out, 0, sizeof(float));
    crf_half_kernel<<<512, 32>>>(em, labels, mask, startT, endT, trans);
    combine_kernel<<<32, 256>>>(labels, endT, (float*)d_out);
}